// round 6
// baseline (speedup 1.0000x reference)
#include <cuda_runtime.h>

#define RMAX 32
#define SMAX 2
#define CZ   128               // channels
#define NPOS 66                // 2*(RMAX+1)
#define NU   132               // combined pos/tok table rows
#define NROW 138               // NU + 6 chain rows
#define UCOLS 128              // columns per work unit

// Folded tables in shared:
//   U[d]    (d<66) = W_pos[d] + W_tok[65]   (same_chain, !same_res -> index d_res)
//   U[66+d] (d<66) = W_tok[d] + W_pos[32]   (same_chain,  same_res -> index 66+d_tok)
//   (!same_chain -> U[65] = W_pos[65] + W_tok[65])
//   C[d]    (d<6)  = W_ch[d] + (d<5 ? w_ent : 0)
__global__ __launch_bounds__(1024, 2)
void relpos_kernel(const int* __restrict__ asym,
                   const int* __restrict__ resi,
                   const int* __restrict__ ent,
                   const int* __restrict__ sym,
                   const int* __restrict__ tok,
                   const float* __restrict__ W,
                   float* __restrict__ out,
                   int N)
{
    extern __shared__ float sW[];              // [NROW*CZ]

    const int tid  = threadIdx.x;
    const int wid  = tid >> 5;
    const int lane = tid & 31;

    // Stage folded tables into shared (once per CTA).
    for (int k = tid; k < NROW * CZ; k += blockDim.x) {
        int row = k >> 7;            // /CZ
        int c   = k & (CZ - 1);
        float v;
        if (row < NPOS) {
            v = W[row * CZ + c] + W[(NPOS + 65) * CZ + c];
        } else if (row < NU) {
            v = W[(NPOS + (row - NPOS)) * CZ + c] + W[32 * CZ + c];
        } else {
            int d = row - NU;
            v = W[(2 * NPOS + 1 + d) * CZ + c];
            if (d < 5) v += W[(2 * NPOS) * CZ + c];
        }
        sW[k] = v;
    }
    __syncthreads();   // the only block barrier

    const float4* sW4  = (const float4*)sW;
    float4*       out4 = (float4*)out;

    const int upr    = N / UCOLS;      // units per row
    const int nUnits = N * upr;

    // Register memoization of the 2-gather+add (valid across units: p is total state).
    int pprev = -1;
    float4 s = make_float4(0.f, 0.f, 0.f, 0.f);

    for (int v = blockIdx.x; v < nUnits; v += gridDim.x) {
        const int i  = v / upr;                   // row
        const int cb = v - i * upr;               // column block
        const int jb = cb * UCOLS + wid * 4;      // this warp's 4 columns

        // Row scalars (uniform L1-hit broadcast loads).
        const int ai = __ldg(&asym[i]), ri = __ldg(&resi[i]);
        const int ei = __ldg(&ent[i]),  si = __ldg(&sym[i]);
        const int ti = __ldg(&tok[i]);

        // Lanes 0..3 compute the packed table index for columns jb+lane.
        int p = 0;
        if (lane < 4) {
            const int j  = jb + lane;
            const int aj = __ldg(&asym[j]), rj = __ldg(&resi[j]);
            const int ej = __ldg(&ent[j]),  sj = __ldg(&sym[j]);
            const int tj = __ldg(&tok[j]);

            bool sc = (ai == aj);
            bool sr = (ri == rj);
            bool se = (ei == ej);

            int u;
            if (sc && sr)  u = NPOS + min(max(ti - tj + RMAX, 0), 2 * RMAX);
            else if (sc)   u = min(max(ri - rj + RMAX, 0), 2 * RMAX);
            else           u = 2 * RMAX + 1;

            int cRel = se ? min(max(si - sj + SMAX, 0), 2 * SMAX) : (2 * SMAX + 1);
            p = u | (cRel << 8);
        }

        const int p0 = __shfl_sync(0xFFFFFFFFu, p, 0);
        const int p1 = __shfl_sync(0xFFFFFFFFu, p, 1);
        const int p2 = __shfl_sync(0xFFFFFFFFu, p, 2);
        const int p3 = __shfl_sync(0xFFFFFFFFu, p, 3);

        const size_t base = ((size_t)i * N + jb) * (CZ / 4) + lane;

        int pq[4] = {p0, p1, p2, p3};
        #pragma unroll
        for (int q = 0; q < 4; ++q) {
            int pc = pq[q];
            if (pc != pprev) {                 // warp-uniform branch
                pprev = pc;
                int rU = pc & 0xFF;
                int rC = NU + (pc >> 8);
                float4 a = sW4[rU * (CZ / 4) + lane];
                float4 c = sW4[rC * (CZ / 4) + lane];
                s.x = a.x + c.x;
                s.y = a.y + c.y;
                s.z = a.z + c.z;
                s.w = a.w + c.w;
            }
            __stcs(&out4[base + (size_t)q * (CZ / 4)], s);
        }
    }
}

extern "C" void kernel_launch(void* const* d_in, const int* in_sizes, int n_in,
                              void* d_out, int out_size)
{
    const int*   asym = (const int*)d_in[0];
    const int*   resi = (const int*)d_in[1];
    const int*   ent  = (const int*)d_in[2];
    const int*   sym  = (const int*)d_in[3];
    const int*   tok  = (const int*)d_in[4];
    const float* W    = (const float*)d_in[5];
    float*       out  = (float*)d_out;

    const int N = in_sizes[0];                  // B*N with B==1 -> 1024

    int nsm = 148;
    cudaDeviceGetAttribute(&nsm, cudaDevAttrMultiProcessorCount, 0);
    const int nUnits = (N / UCOLS) * N;
    int grid = 2 * nsm;
    if (grid > nUnits) grid = nUnits;

    const int smem_bytes = NROW * CZ * (int)sizeof(float);

    cudaFuncSetAttribute(relpos_kernel,
                         cudaFuncAttributeMaxDynamicSharedMemorySize, smem_bytes);

    relpos_kernel<<<grid, 1024, smem_bytes>>>(asym, resi, ent, sym, tok, W, out, N);
}

// round 7
// speedup vs baseline: 1.3891x; 1.3891x over previous
#include <cuda_runtime.h>
#include <cstdint>

#define RMAX 32
#define SMAX 2
#define CZ    128              // channels
#define NPOS  66               // 2*(RMAX+1)
#define NU    132              // combined pos/tok table rows
#define NROW  138              // NU + 6 chain rows
#define HALF  512              // columns per CTA work unit
#define TCOLS 64               // columns per TMA tile
#define TILE_BYTES (TCOLS * CZ * 4)   // 32 KB

// Folded table in device global (built once per launch by build_table):
//   U[d]    (d<66) = W_pos[d] + W_tok[65]
//   U[66+d] (d<66) = W_tok[d] + W_pos[32]
//   C[d]    (d<6)  = W_ch[d] + (d<5 ? w_ent : 0)
__device__ float gU[NROW * CZ];

__global__ void build_table(const float* __restrict__ W)
{
    int k = blockIdx.x * blockDim.x + threadIdx.x;
    if (k >= NROW * CZ) return;
    int row = k >> 7;
    int c   = k & (CZ - 1);
    float v;
    if (row < NPOS) {
        v = W[row * CZ + c] + W[(NPOS + 65) * CZ + c];
    } else if (row < NU) {
        v = W[row * CZ + c] + W[32 * CZ + c];   // W_tok rows are at the same offset
    } else {
        int d = row - NU;
        v = W[(2 * NPOS + 1 + d) * CZ + c];
        if (d < 5) v += W[(2 * NPOS) * CZ + c];
    }
    gU[k] = v;
}

__device__ __forceinline__ int pack_idx(int ai, int ri, int ei, int si, int ti,
                                        int aj, int rj, int ej, int sj, int tj)
{
    bool sc = (ai == aj);
    bool sr = (ri == rj);
    bool se = (ei == ej);
    int u;
    if (sc && sr)  u = NPOS + min(max(ti - tj + RMAX, 0), 2 * RMAX);
    else if (sc)   u = min(max(ri - rj + RMAX, 0), 2 * RMAX);
    else           u = 2 * RMAX + 1;
    int cRel = se ? min(max(si - sj + SMAX, 0), 2 * SMAX) : (2 * SMAX + 1);
    return u | (cRel << 8);
}

// Main kernel: requires N == 1024 (blockDim 1024, HALF=512). Fallback otherwise.
__global__ __launch_bounds__(1024, 2)
void relpos_tma(const int* __restrict__ asym,
                const int* __restrict__ resi,
                const int* __restrict__ ent,
                const int* __restrict__ sym,
                const int* __restrict__ tok,
                float* __restrict__ out,
                int N)
{
    extern __shared__ char smem[];
    float* tiles = (float*)smem;                        // [2][TILE_BYTES/4]
    int*   sI    = (int*)(smem + 2 * TILE_BYTES);       // [HALF]

    uint32_t sbase;
    asm("{ .reg .u64 t; cvta.to.shared.u64 t, %1; cvt.u32.u64 %0, t; }"
        : "=r"(sbase) : "l"(smem));

    const int tid  = threadIdx.x;
    const int lane = tid & 31;

    // Thread tid owns global column j = tid (N == blockDim == 1024).
    const int aj = asym[tid], rj = resi[tid], ej = ent[tid];
    const int sj = sym[tid],  tj = tok[tid];

    const float4* U4 = (const float4*)gU;

    // Cross-unit memoization of the 2-gather+add (p is the complete state).
    int pprev = -1;
    float4 s = make_float4(0.f, 0.f, 0.f, 0.f);

    const int upr    = N / HALF;       // 2
    const int nUnits = N * upr;        // 2048

    for (int v = blockIdx.x; v < nUnits; v += gridDim.x) {
        const int i = v / upr;
        const int h = v - i * upr;

        const int ai = __ldg(&asym[i]), ri = __ldg(&resi[i]);
        const int ei = __ldg(&ent[i]),  si = __ldg(&sym[i]);
        const int ti = __ldg(&tok[i]);

        // Stage packed indices for this half-row (threads owning these columns).
        if ((tid >> 9) == h)
            sI[tid & (HALF - 1)] = pack_idx(ai, ri, ei, si, ti, aj, rj, ej, sj, tj);

        const size_t unit_base = ((size_t)i * N + (size_t)h * HALF) * CZ; // floats

        #pragma unroll 1
        for (int t = 0; t < HALF / TCOLS; ++t) {        // 8 tiles
            const int      b       = t & 1;
            float*         buf     = tiles + b * (TILE_BYTES / 4);
            const uint32_t bufaddr = sbase + b * TILE_BYTES;

            // Ensure the TMA that last read this buffer has finished its smem read.
            if (tid == 0)
                asm volatile("cp.async.bulk.wait_group.read 1;" ::: "memory");
            __syncthreads();   // buffer free for all; sI visible (t==0)

            // Fill the 64-col tile: 2048 float4s, 2 per thread.
            #pragma unroll
            for (int k = 0; k < 2; ++k) {
                const int g   = tid + k * 1024;
                const int col = g >> 5;                 // 0..63
                const int p   = sI[t * TCOLS + col];    // warp-uniform broadcast
                if (p != pprev) {                       // warp-uniform branch
                    pprev = p;
                    const int rU = p & 0xFF;
                    const int rC = NU + (p >> 8);
                    float4 a = __ldg(&U4[rU * (CZ / 4) + lane]);
                    float4 c = __ldg(&U4[rC * (CZ / 4) + lane]);
                    s.x = a.x + c.x;
                    s.y = a.y + c.y;
                    s.z = a.z + c.z;
                    s.w = a.w + c.w;
                }
                ((float4*)buf)[col * (CZ / 4) + lane] = s;   // STS.128, no conflicts
            }
            __syncthreads();   // tile complete

            if (tid == 0) {
                asm volatile("fence.proxy.async.shared::cta;" ::: "memory");
                const float* dst = out + unit_base + (size_t)t * TCOLS * CZ;
                uint64_t gdst;
                asm("cvta.to.global.u64 %0, %1;" : "=l"(gdst) : "l"(dst));
                asm volatile(
                    "cp.async.bulk.global.shared::cta.bulk_group [%0], [%1], %2;"
                    :: "l"(gdst), "r"(bufaddr), "r"((uint32_t)TILE_BYTES)
                    : "memory");
                asm volatile("cp.async.bulk.commit_group;" ::: "memory");
            }
        }
    }
    // Outstanding bulk stores complete before grid completion is visible.
}

// Generic fallback (any N): one thread per output float4.
__global__ void relpos_simple(const int* __restrict__ asym,
                              const int* __restrict__ resi,
                              const int* __restrict__ ent,
                              const int* __restrict__ sym,
                              const int* __restrict__ tok,
                              float* __restrict__ out,
                              int N)
{
    long long idx = (long long)blockIdx.x * blockDim.x + threadIdx.x;
    long long tot = (long long)N * N * (CZ / 4);
    if (idx >= tot) return;
    int f4 = (int)(idx & (CZ / 4 - 1));
    long long ij = idx >> 5;
    int j = (int)(ij % N);
    int i = (int)(ij / N);

    int p = pack_idx(asym[i], resi[i], ent[i], sym[i], tok[i],
                     asym[j], resi[j], ent[j], sym[j], tok[j]);
    int rU = p & 0xFF;
    int rC = NU + (p >> 8);
    const float4* U4 = (const float4*)gU;
    float4 a = U4[rU * (CZ / 4) + f4];
    float4 c = U4[rC * (CZ / 4) + f4];
    float4 s;
    s.x = a.x + c.x; s.y = a.y + c.y; s.z = a.z + c.z; s.w = a.w + c.w;
    ((float4*)out)[idx] = s;
}

extern "C" void kernel_launch(void* const* d_in, const int* in_sizes, int n_in,
                              void* d_out, int out_size)
{
    const int*   asym = (const int*)d_in[0];
    const int*   resi = (const int*)d_in[1];
    const int*   ent  = (const int*)d_in[2];
    const int*   sym  = (const int*)d_in[3];
    const int*   tok  = (const int*)d_in[4];
    const float* W    = (const float*)d_in[5];
    float*       out  = (float*)d_out;

    const int N = in_sizes[0];                  // B*N with B==1 -> 1024

    build_table<<<(NROW * CZ + 255) / 256, 256>>>(W);

    if (N == 1024) {
        int nsm = 148;
        cudaDeviceGetAttribute(&nsm, cudaDevAttrMultiProcessorCount, 0);
        const int nUnits = (N / HALF) * N;
        int grid = 2 * nsm;
        if (grid > nUnits) grid = nUnits;

        const int smem_bytes = 2 * TILE_BYTES + HALF * (int)sizeof(int);
        cudaFuncSetAttribute(relpos_tma,
                             cudaFuncAttributeMaxDynamicSharedMemorySize, smem_bytes);
        relpos_tma<<<grid, 1024, smem_bytes>>>(asym, resi, ent, sym, tok, out, N);
    } else {
        long long tot = (long long)N * N * (CZ / 4);
        int grid = (int)((tot + 255) / 256);
        relpos_simple<<<grid, 256>>>(asym, resi, ent, sym, tok, out, N);
    }
}

// round 8
// speedup vs baseline: 1.4220x; 1.0237x over previous
#include <cuda_runtime.h>
#include <cstdint>

#define RMAX 32
#define SMAX 2
#define CZ    128              // channels
#define NPOS  66               // 2*(RMAX+1)
#define NN    1024             // fast-path N
#define TCOLS 64               // columns per TMA tile / work unit
#define UPR   (NN / TCOLS)     // 16 units per row
#define TILE_BYTES (TCOLS * CZ * 4)   // 32 KB
#define NBUF  3

// Combined-table identity (NPOS==66 makes U rows coincide with W rows):
//   u < 66   : p-vec = W[u]      + W_tok[65]            (= W[131])
//   66<=u<132: p-vec = W[u]      + W_pos[32]            (= W[32])
//   chain    : + W[133 + cRel] + (cRel<5 ? W[132] : 0)
// The three fixed addend vectors live in registers; memo-miss needs only 2 LDG.

__device__ __forceinline__ int pack_idx(int ai, int ri, int ei, int si, int ti,
                                        int aj, int rj, int ej, int sj, int tj)
{
    bool sc = (ai == aj);
    bool sr = (ri == rj);
    bool se = (ei == ej);
    int u;
    if (sc && sr)  u = NPOS + min(max(ti - tj + RMAX, 0), 2 * RMAX);
    else if (sc)   u = min(max(ri - rj + RMAX, 0), 2 * RMAX);
    else           u = 2 * RMAX + 1;
    int cRel = se ? min(max(si - sj + SMAX, 0), 2 * SMAX) : (2 * SMAX + 1);
    return u | (cRel << 8);
}

__global__ __launch_bounds__(1024, 2)
void relpos_tma(const int* __restrict__ asym,
                const int* __restrict__ resi,
                const int* __restrict__ ent,
                const int* __restrict__ sym,
                const int* __restrict__ tok,
                const float* __restrict__ W,
                float* __restrict__ out)
{
    extern __shared__ char smem[];
    float* tiles = (float*)smem;                        // [NBUF][TILE_BYTES/4]
    int*   sI    = (int*)(smem + NBUF * TILE_BYTES);    // [TCOLS]

    uint32_t sbase;
    asm("{ .reg .u64 t; cvta.to.shared.u64 t, %1; cvt.u32.u64 %0, t; }"
        : "=r"(sbase) : "l"(smem));

    const int tid  = threadIdx.x;
    const int lane = tid & 31;

    const float4* W4 = (const float4*)W;
    // Fixed fold addends in registers (per-lane float4 = channels lane*4..+3).
    const float4 regT65 = __ldg(&W4[(NPOS + 65) * 32 + lane]);   // W_tok[65]
    const float4 regP32 = __ldg(&W4[32 * 32 + lane]);            // W_pos[32]
    const float4 regEnt = __ldg(&W4[(2 * NPOS) * 32 + lane]);    // w_ent

    // Thread tid permanently owns global column j = tid (NN == blockDim).
    const int aj = asym[tid], rj = resi[tid], ej = ent[tid];
    const int sj = sym[tid],  tj = tok[tid];

    // Cross-unit memoization: p is the complete lookup state.
    int pprev = -1;
    float4 s = make_float4(0.f, 0.f, 0.f, 0.f);

    int b = 0;
    for (int v = blockIdx.x; v < NN * UPR; v += gridDim.x) {
        const int i  = v >> 4;            // row       (UPR == 16)
        const int cb = v & (UPR - 1);     // column block

        const int ai = __ldg(&asym[i]), ri = __ldg(&resi[i]);
        const int ei = __ldg(&ent[i]),  si = __ldg(&sym[i]);
        const int ti = __ldg(&tok[i]);

        // The 64 threads owning this tile's columns stage packed indices.
        if ((tid >> 6) == cb)
            sI[tid & (TCOLS - 1)] = pack_idx(ai, ri, ei, si, ti, aj, rj, ej, sj, tj);

        float*         buf     = tiles + b * (TILE_BYTES / 4);
        const uint32_t bufaddr = sbase + b * TILE_BYTES;

        // Buffer b free once at most NBUF-1 prior bulk groups still read smem.
        if (tid == 0)
            asm volatile("cp.async.bulk.wait_group.read %0;" :: "n"(NBUF - 1) : "memory");
        __syncthreads();   // buffer free + sI visible to all

        // Fill the 64-col tile: 2048 float4s, 2 per thread.
        #pragma unroll
        for (int k = 0; k < 2; ++k) {
            const int col = (tid + k * 1024) >> 5;      // 0..63
            const int p   = sI[col];                    // warp-uniform broadcast
            if (p != pprev) {                           // warp-uniform branch
                pprev = p;
                const int rU   = p & 0xFF;
                const int cRel = p >> 8;
                float4 a  = __ldg(&W4[rU * 32 + lane]);
                float4 ch = __ldg(&W4[(2 * NPOS + 1 + cRel) * 32 + lane]);
                float4 x1 = (rU < NPOS) ? regT65 : regP32;
                s.x = a.x + x1.x + ch.x;
                s.y = a.y + x1.y + ch.y;
                s.z = a.z + x1.z + ch.z;
                s.w = a.w + x1.w + ch.w;
                if (cRel < 5) {
                    s.x += regEnt.x; s.y += regEnt.y;
                    s.z += regEnt.z; s.w += regEnt.w;
                }
            }
            ((float4*)buf)[col * 32 + lane] = s;        // STS.128, conflict-free
        }
        __syncthreads();   // tile complete

        if (tid == 0) {
            asm volatile("fence.proxy.async.shared::cta;" ::: "memory");
            const float* dst = out + ((size_t)i * NN + (size_t)cb * TCOLS) * CZ;
            uint64_t gdst;
            asm("cvta.to.global.u64 %0, %1;" : "=l"(gdst) : "l"(dst));
            asm volatile(
                "cp.async.bulk.global.shared::cta.bulk_group [%0], [%1], %2;"
                :: "l"(gdst), "r"(bufaddr), "r"((uint32_t)TILE_BYTES)
                : "memory");
            asm volatile("cp.async.bulk.commit_group;" ::: "memory");
        }
        if (++b == NBUF) b = 0;
    }
    // Outstanding bulk stores complete before kernel completion is visible.
}

// Generic fallback (any N): one thread per output float4, direct 4-gather.
__global__ void relpos_simple(const int* __restrict__ asym,
                              const int* __restrict__ resi,
                              const int* __restrict__ ent,
                              const int* __restrict__ sym,
                              const int* __restrict__ tok,
                              const float* __restrict__ W,
                              float* __restrict__ out,
                              int N)
{
    long long idx = (long long)blockIdx.x * blockDim.x + threadIdx.x;
    long long tot = (long long)N * N * (CZ / 4);
    if (idx >= tot) return;
    int f4 = (int)(idx & (CZ / 4 - 1));
    long long ij = idx >> 5;
    int j = (int)(ij % N);
    int i = (int)(ij / N);

    int p = pack_idx(asym[i], resi[i], ent[i], sym[i], tok[i],
                     asym[j], resi[j], ent[j], sym[j], tok[j]);
    int rU   = p & 0xFF;
    int cRel = p >> 8;
    const float4* W4 = (const float4*)W;
    float4 a  = W4[rU * 32 + f4];
    float4 x1 = (rU < NPOS) ? W4[(NPOS + 65) * 32 + f4] : W4[32 * 32 + f4];
    float4 ch = W4[(2 * NPOS + 1 + cRel) * 32 + f4];
    float4 s;
    s.x = a.x + x1.x + ch.x;
    s.y = a.y + x1.y + ch.y;
    s.z = a.z + x1.z + ch.z;
    s.w = a.w + x1.w + ch.w;
    if (cRel < 5) {
        float4 e = W4[(2 * NPOS) * 32 + f4];
        s.x += e.x; s.y += e.y; s.z += e.z; s.w += e.w;
    }
    ((float4*)out)[idx] = s;
}

extern "C" void kernel_launch(void* const* d_in, const int* in_sizes, int n_in,
                              void* d_out, int out_size)
{
    const int*   asym = (const int*)d_in[0];
    const int*   resi = (const int*)d_in[1];
    const int*   ent  = (const int*)d_in[2];
    const int*   sym  = (const int*)d_in[3];
    const int*   tok  = (const int*)d_in[4];
    const float* W    = (const float*)d_in[5];
    float*       out  = (float*)d_out;

    const int N = in_sizes[0];                  // B*N with B==1 -> 1024

    if (N == NN) {
        int nsm = 148;
        cudaDeviceGetAttribute(&nsm, cudaDevAttrMultiProcessorCount, 0);
        int grid = 2 * nsm;
        if (grid > NN * UPR) grid = NN * UPR;

        const int smem_bytes = NBUF * TILE_BYTES + TCOLS * (int)sizeof(int);
        cudaFuncSetAttribute(relpos_tma,
                             cudaFuncAttributeMaxDynamicSharedMemorySize, smem_bytes);
        relpos_tma<<<grid, 1024, smem_bytes>>>(asym, resi, ent, sym, tok, W, out);
    } else {
        long long tot = (long long)N * N * (CZ / 4);
        int grid = (int)((tot + 255) / 256);
        relpos_simple<<<grid, 256>>>(asym, resi, ent, sym, tok, W, out, N);
    }
}